// round 15
// baseline (speedup 1.0000x reference)
#include <cuda_runtime.h>
#include <cuda_bf16.h>
#include <cstdint>

// ---------------------------------------------------------------------------
// Problem constants
// ---------------------------------------------------------------------------
static constexpr int Bc = 32;
static constexpr int Nc = 1024;
static constexpr int Dc = 768;
static constexpr int Kc = 512;
static constexpr int Mc = Bc * Nc;   // 32768 tokens

// ---------------------------------------------------------------------------
// Global scratch (static __device__ — allocation-guard safe)
// ---------------------------------------------------------------------------
__device__ __align__(16) float         g_L[(size_t)Kc * Mc];      // logits [K][M]
__device__ float                       g_csq[Kc];
__device__ __align__(16) float         g_pmax[(size_t)4 * Mc];    // per-kblock max
__device__ __align__(16) float         g_psum[(size_t)4 * Mc];    // per-kblock sum
__device__ __align__(16) __nv_bfloat16 g_St_hi[(size_t)Bc * Kc * Nc];
__device__ __align__(16) __nv_bfloat16 g_St_lo[(size_t)Bc * Kc * Nc];
__device__ __align__(16) __nv_bfloat16 g_Xd_hi[(size_t)Mc * Dc];
__device__ __align__(16) __nv_bfloat16 g_Xd_lo[(size_t)Mc * Dc];
__device__ __align__(16) __nv_bfloat16 g_C_hi[(size_t)Kc * Dc];   // holds 2*C split
__device__ __align__(16) __nv_bfloat16 g_C_lo[(size_t)Kc * Dc];

// ---------------------------------------------------------------------------
// Primitives (baseline sm_80+ PTX)
// ---------------------------------------------------------------------------
__device__ __forceinline__ uint32_t smem_u32(const void* p) {
    uint32_t a;
    asm("{ .reg .u64 t; cvta.to.shared.u64 t, %1; cvt.u32.u64 %0, t; }" : "=r"(a) : "l"(p));
    return a;
}
__device__ __forceinline__ void ldsm4(uint32_t (&r)[4], uint32_t addr) {
    asm volatile("ldmatrix.sync.aligned.m8n8.x4.shared.b16 {%0,%1,%2,%3}, [%4];"
                 : "=r"(r[0]), "=r"(r[1]), "=r"(r[2]), "=r"(r[3]) : "r"(addr));
}
__device__ __forceinline__ void ldsm4t(uint32_t (&r)[4], uint32_t addr) {
    asm volatile("ldmatrix.sync.aligned.m8n8.x4.trans.shared.b16 {%0,%1,%2,%3}, [%4];"
                 : "=r"(r[0]), "=r"(r[1]), "=r"(r[2]), "=r"(r[3]) : "r"(addr));
}
__device__ __forceinline__ void mma_bf16(float (&d)[4], const uint32_t (&a)[4],
                                         const uint32_t (&b)[2]) {
    asm volatile(
        "mma.sync.aligned.m16n8k16.row.col.f32.bf16.bf16.f32 "
        "{%0,%1,%2,%3}, {%4,%5,%6,%7}, {%8,%9}, {%0,%1,%2,%3};"
        : "+f"(d[0]), "+f"(d[1]), "+f"(d[2]), "+f"(d[3])
        : "r"(a[0]), "r"(a[1]), "r"(a[2]), "r"(a[3]), "r"(b[0]), "r"(b[1]));
}
__device__ __forceinline__ void cp16(uint32_t saddr, const void* g) {
    asm volatile("cp.async.cg.shared.global [%0], [%1], 16;" :: "r"(saddr), "l"(g));
}
#define CP_COMMIT() asm volatile("cp.async.commit_group;" ::: "memory")
#define CP_WAIT0()  asm volatile("cp.async.wait_group 0;" ::: "memory")

// ---------------------------------------------------------------------------
// GEMM1 geometry: CTA 128x128, BK=48 (16 chunks), TP48=56 pad, 2 stages.
// 4 tiles x 14336B x 2 stages = 114688B -> still 2 CTAs/SM.
// ---------------------------------------------------------------------------
static constexpr int TP1 = 56;
static constexpr int T1_ELEMS = 128 * TP1;            // 7168
static constexpr int T1B = T1_ELEMS * 2;               // 14336 bytes
static constexpr int BUF1 = 4 * T1B;                   // 57344 bytes per stage
static constexpr int SMEM_G1 = 2 * BUF1;               // 114688 bytes

// GEMM2 geometry (unchanged): BK=32, TP=40 / BTP=136, 2 stages, 75776B.
static constexpr int TP = 40;
static constexpr int TILE_ELEMS = 128 * TP;            // 5120
static constexpr int TILEB = TILE_ELEMS * 2;           // 10240 bytes
static constexpr int BTP = 136;
static constexpr int B_TILEB = 32 * BTP * 2;           // 8704 bytes
static constexpr int BUF2 = 2 * TILEB + 2 * B_TILEB;   // 37888 bytes per stage
static constexpr int SMEM_G2 = 2 * BUF2;               // 75776 bytes

// ---------------------------------------------------------------------------
// Kernel 1: fused — csq[k] = sum_d C[k,d]^2 AND (2*C) hi/lo bf16 split
// ---------------------------------------------------------------------------
__global__ __launch_bounds__(256) void csq_split_kernel(const float* __restrict__ C) {
    const int k = blockIdx.x, t = threadIdx.x;
    const float* row = C + (size_t)k * Dc;
    __nv_bfloat16* Hr = g_C_hi + (size_t)k * Dc;
    __nv_bfloat16* Lr = g_C_lo + (size_t)k * Dc;
    float s = 0.f;
    #pragma unroll
    for (int i = 0; i < 3; i++) {            // Dc = 768 = 3*256
        int d = t + 256 * i;
        float v = row[d];
        s += v * v;
        float v2 = 2.f * v;                  // fold the 2x into the operand
        __nv_bfloat16 h = __float2bfloat16(v2);
        __nv_bfloat16 l = __float2bfloat16(v2 - __bfloat162float(h));
        Hr[d] = h;
        Lr[d] = l;
    }
    #pragma unroll
    for (int o = 16; o > 0; o >>= 1) s += __shfl_xor_sync(0xffffffffu, s, o);
    __shared__ float red[8];
    if ((t & 31) == 0) red[t >> 5] = s;
    __syncthreads();
    if (t == 0) {
        float tot = 0.f;
        #pragma unroll
        for (int w = 0; w < 8; w++) tot += red[w];
        g_csq[k] = tot;
    }
}

// ---------------------------------------------------------------------------
// Kernel 2: streaming fp32 -> hi/lo bf16 split (X)
// ---------------------------------------------------------------------------
__global__ __launch_bounds__(256) void split_kernel(const float* __restrict__ src,
                                                    __nv_bfloat16* __restrict__ h,
                                                    __nv_bfloat16* __restrict__ l) {
    size_t i = ((size_t)blockIdx.x * 256 + threadIdx.x) * 4;
    float4 v = *(const float4*)(src + i);
    float x[4] = {v.x, v.y, v.z, v.w};
    uint32_t hb[4], lb[4];
    #pragma unroll
    for (int j = 0; j < 4; j++) {
        __nv_bfloat16 hh = __float2bfloat16(x[j]);
        float r = x[j] - __bfloat162float(hh);
        __nv_bfloat16 ll = __float2bfloat16(r);
        hb[j] = (uint32_t)__bfloat16_as_ushort(hh);
        lb[j] = (uint32_t)__bfloat16_as_ushort(ll);
    }
    *(uint2*)(h + i) = make_uint2(hb[0] | (hb[1] << 16), hb[2] | (hb[3] << 16));
    *(uint2*)(l + i) = make_uint2(lb[0] | (lb[1] << 16), lb[2] | (lb[3] << 16));
}

// ---------------------------------------------------------------------------
// GEMM1 MMA phase: BK=48 (3 k-steps), A = 2C[k][d], B = Xd[m][d]; x4 B ldsm
// ---------------------------------------------------------------------------
__device__ __forceinline__ void mma_chunk1(float (&acc)[4][4][4], uint32_t ubase,
                                           uint32_t cb, uint32_t aoff, uint32_t b4off) {
    #pragma unroll
    for (int ks = 0; ks < 3; ks++) {
        uint32_t ah[4][4], al[4][4], bh[4][2], bl[4][2];
        #pragma unroll
        for (int mi = 0; mi < 4; mi++) {
            uint32_t off = aoff + (uint32_t)(mi * 16 * TP1 + ks * 16) * 2;
            ldsm4(ah[mi], ubase + cb + off);
            ldsm4(al[mi], ubase + cb + T1B + off);
        }
        #pragma unroll
        for (int np = 0; np < 2; np++) {
            uint32_t rh[4], rl[4];
            uint32_t off = b4off + (uint32_t)(np * 16 * TP1 + ks * 16) * 2;
            ldsm4(rh, ubase + cb + 2 * T1B + off);
            ldsm4(rl, ubase + cb + 3 * T1B + off);
            bh[np*2][0] = rh[0]; bh[np*2][1] = rh[1];
            bh[np*2+1][0] = rh[2]; bh[np*2+1][1] = rh[3];
            bl[np*2][0] = rl[0]; bl[np*2][1] = rl[1];
            bl[np*2+1][0] = rl[2]; bl[np*2+1][1] = rl[3];
        }
        #pragma unroll
        for (int mi = 0; mi < 4; mi++)
            #pragma unroll
            for (int ni = 0; ni < 4; ni++) {
                mma_bf16(acc[mi][ni], ah[mi], bh[ni]);
                mma_bf16(acc[mi][ni], ah[mi], bl[ni]);
                mma_bf16(acc[mi][ni], al[mi], bh[ni]);
            }
    }
}

// ---------------------------------------------------------------------------
// Kernel 3: GEMM1 — Lt[k][m] = <2C_k, X_m> - csq[k], + partial softmax stats
// ---------------------------------------------------------------------------
__global__ __launch_bounds__(256, 2) void gemm1_mma() {
    extern __shared__ __align__(16) char dsm[];
    const int tid = threadIdx.x;
    const int wid = tid >> 5, lane = tid & 31;
    const int k0 = blockIdx.x * 128;
    const int m0 = blockIdx.y * 128;
    const int wm = (wid & 1) * 64;
    const int wn = (wid >> 1) * 32;

    const uint32_t ubase = smem_u32(dsm);
    const int a_r = lane & 15;
    const int a_c = (lane & 16) ? 8 : 0;
    const uint32_t aoff = (uint32_t)((wm + a_r) * TP1 + a_c) * 2;
    const uint32_t b4off =
        (uint32_t)((wn + (lane & 7) + ((lane >> 4) & 1) * 8) * TP1 + ((lane >> 3) & 1) * 8) * 2;

    static constexpr int NCH = Dc / 48;              // 16

    float acc[4][4][4] = {};

    // loader: 128 rows x 6 col8-groups = 768 cp16 per tile, 3 per thread
    auto issue = [&](int c, uint32_t buf) {
        #pragma unroll
        for (int i = 0; i < 3; i++) {
            int slot = tid + 256 * i;
            int row = slot / 6;
            int col = (slot % 6) * 8;
            int db = c * 48 + col;
            uint32_t so = buf + (uint32_t)(row * TP1 + col) * 2;
            cp16(ubase + so,            g_C_hi  + (size_t)(k0 + row) * Dc + db);
            cp16(ubase + so + T1B,      g_C_lo  + (size_t)(k0 + row) * Dc + db);
            cp16(ubase + so + 2 * T1B,  g_Xd_hi + (size_t)(m0 + row) * Dc + db);
            cp16(ubase + so + 3 * T1B,  g_Xd_lo + (size_t)(m0 + row) * Dc + db);
        }
    };

    issue(0, 0);
    CP_COMMIT();
    for (int c = 0; c < NCH; c++) {
        CP_WAIT0();
        __syncthreads();
        if (c + 1 < NCH) {
            issue(c + 1, (uint32_t)((c + 1) & 1) * BUF1);
            CP_COMMIT();
        }
        mma_chunk1(acc, ubase, (uint32_t)(c & 1) * BUF1, aoff, b4off);
    }

    // --- epilogue: logits = acc - csq (the 2x is folded into C) ---
    float cs0v[4], cs1v[4];
    #pragma unroll
    for (int mi = 0; mi < 4; mi++) {
        int kr = k0 + wm + mi * 16 + (lane >> 2);
        cs0v[mi] = g_csq[kr];
        cs1v[mi] = g_csq[kr + 8];
    }
    #pragma unroll
    for (int mi = 0; mi < 4; mi++)
        #pragma unroll
        for (int ni = 0; ni < 4; ni++) {
            acc[mi][ni][0] -= cs0v[mi];
            acc[mi][ni][1] -= cs0v[mi];
            acc[mi][ni][2] -= cs1v[mi];
            acc[mi][ni][3] -= cs1v[mi];
        }
    #pragma unroll
    for (int mi = 0; mi < 4; mi++) {
        const int kr = k0 + wm + mi * 16 + (lane >> 2);
        #pragma unroll
        for (int ni = 0; ni < 4; ni++) {
            const int mc = m0 + wn + ni * 8 + (lane & 3) * 2;
            *(float2*)(g_L + (size_t)kr * Mc + mc) =
                make_float2(acc[mi][ni][0], acc[mi][ni][1]);
            *(float2*)(g_L + (size_t)(kr + 8) * Mc + mc) =
                make_float2(acc[mi][ni][2], acc[mi][ni][3]);
        }
    }

    // --- partial softmax stats over this CTA's 128 k-rows ---
    __syncthreads();
    float* pm2 = (float*)dsm;            // [2][128]
    float* ps2 = pm2 + 256;              // [2][128]
    #pragma unroll
    for (int ni = 0; ni < 4; ni++) {
        float m0v = -3.4e38f, m1v = -3.4e38f;
        #pragma unroll
        for (int mi = 0; mi < 4; mi++) {
            m0v = fmaxf(m0v, fmaxf(acc[mi][ni][0], acc[mi][ni][2]));
            m1v = fmaxf(m1v, fmaxf(acc[mi][ni][1], acc[mi][ni][3]));
        }
        #pragma unroll
        for (int o = 4; o <= 16; o <<= 1) {
            m0v = fmaxf(m0v, __shfl_xor_sync(0xffffffffu, m0v, o));
            m1v = fmaxf(m1v, __shfl_xor_sync(0xffffffffu, m1v, o));
        }
        float s0 = 0.f, s1 = 0.f;
        #pragma unroll
        for (int mi = 0; mi < 4; mi++) {
            s0 += __expf(acc[mi][ni][0] - m0v) + __expf(acc[mi][ni][2] - m0v);
            s1 += __expf(acc[mi][ni][1] - m1v) + __expf(acc[mi][ni][3] - m1v);
        }
        #pragma unroll
        for (int o = 4; o <= 16; o <<= 1) {
            s0 += __shfl_xor_sync(0xffffffffu, s0, o);
            s1 += __shfl_xor_sync(0xffffffffu, s1, o);
        }
        if ((lane >> 2) == 0) {
            int col = wn + ni * 8 + (lane & 3) * 2;
            int h = (wid & 1) * 128;
            pm2[h + col]     = m0v;  ps2[h + col]     = s0;
            pm2[h + col + 1] = m1v;  ps2[h + col + 1] = s1;
        }
    }
    __syncthreads();
    if (tid < 128) {
        float Ma = pm2[tid], Mb = pm2[128 + tid];
        float M = fmaxf(Ma, Mb);
        float S = ps2[tid] * __expf(Ma - M) + ps2[128 + tid] * __expf(Mb - M);
        g_pmax[(size_t)blockIdx.x * Mc + m0 + tid] = M;
        g_psum[(size_t)blockIdx.x * Mc + m0 + tid] = S;
    }
}

// ---------------------------------------------------------------------------
// Kernel 4: softmax apply — k-split across grid.y; warp owns an 8-k sub-slice.
// ---------------------------------------------------------------------------
__global__ __launch_bounds__(256) void softmaxT_kernel() {
    const int lane = threadIdx.x & 31;
    const int warp = threadIdx.x >> 5;               // 0..7
    const int m0 = blockIdx.x * 64 + lane * 2;
    const int b  = m0 >> 10;
    const int n0 = m0 & 1023;
    const int kb = blockIdx.y * 64 + warp * 8;

    float gm0 = -3.4e38f, gm1 = -3.4e38f, gs0 = 0.f, gs1 = 0.f;
    #pragma unroll
    for (int p = 0; p < 4; p++) {
        float2 pM = *(const float2*)(g_pmax + (size_t)p * Mc + m0);
        float2 pS = *(const float2*)(g_psum + (size_t)p * Mc + m0);
        float nm0 = fmaxf(gm0, pM.x);
        gs0 = gs0 * __expf(gm0 - nm0) + pS.x * __expf(pM.x - nm0);
        gm0 = nm0;
        float nm1 = fmaxf(gm1, pM.y);
        gs1 = gs1 * __expf(gm1 - nm1) + pS.y * __expf(pM.y - nm1);
        gm1 = nm1;
    }
    const float inv0 = 1.0f / gs0, inv1 = 1.0f / gs1;

    __nv_bfloat16* SH = g_St_hi + (size_t)b * Kc * Nc + n0;
    __nv_bfloat16* SL = g_St_lo + (size_t)b * Kc * Nc + n0;
    #pragma unroll
    for (int k = kb; k < kb + 8; k++) {
        float2 v = *(const float2*)(g_L + (size_t)k * Mc + m0);
        float p0 = __expf(v.x - gm0) * inv0;
        float p1 = __expf(v.y - gm1) * inv1;
        __nv_bfloat16 h0 = __float2bfloat16(p0);
        __nv_bfloat16 l0 = __float2bfloat16(p0 - __bfloat162float(h0));
        __nv_bfloat16 h1 = __float2bfloat16(p1);
        __nv_bfloat16 l1 = __float2bfloat16(p1 - __bfloat162float(h1));
        *(uint32_t*)(SH + (size_t)k * Nc) =
            (uint32_t)__bfloat16_as_ushort(h0) | ((uint32_t)__bfloat16_as_ushort(h1) << 16);
        *(uint32_t*)(SL + (size_t)k * Nc) =
            (uint32_t)__bfloat16_as_ushort(l0) | ((uint32_t)__bfloat16_as_ushort(l1) << 16);
    }
}

// ---------------------------------------------------------------------------
// GEMM2 MMA phase: A = St [k][n] (non-trans), B = Xd [n][d] via x4 TRANS ldsm
// ---------------------------------------------------------------------------
__device__ __forceinline__ void mma_chunk2(float (&acc)[4][4][4], uint32_t ubase,
                                           uint32_t cb, uint32_t aoff,
                                           uint32_t bt4off, int wn) {
    #pragma unroll
    for (int ks = 0; ks < 2; ks++) {
        uint32_t ah[4][4], al[4][4], bh[4][2], bl[4][2];
        #pragma unroll
        for (int mi = 0; mi < 4; mi++) {
            uint32_t off = aoff + (uint32_t)(mi * 16 * TP + ks * 16) * 2;
            ldsm4(ah[mi], ubase + cb + off);
            ldsm4(al[mi], ubase + cb + TILEB + off);
        }
        #pragma unroll
        for (int np = 0; np < 2; np++) {
            uint32_t rh[4], rl[4];
            uint32_t off = bt4off + (uint32_t)(ks * 16 * BTP + wn + np * 16) * 2;
            ldsm4t(rh, ubase + cb + 2 * TILEB + off);
            ldsm4t(rl, ubase + cb + 2 * TILEB + B_TILEB + off);
            bh[np*2][0] = rh[0]; bh[np*2][1] = rh[1];
            bh[np*2+1][0] = rh[2]; bh[np*2+1][1] = rh[3];
            bl[np*2][0] = rl[0]; bl[np*2][1] = rl[1];
            bl[np*2+1][0] = rl[2]; bl[np*2+1][1] = rl[3];
        }
        #pragma unroll
        for (int mi = 0; mi < 4; mi++)
            #pragma unroll
            for (int ni = 0; ni < 4; ni++) {
                mma_bf16(acc[mi][ni], ah[mi], bh[ni]);
                mma_bf16(acc[mi][ni], ah[mi], bl[ni]);
                mma_bf16(acc[mi][ni], al[mi], bh[ni]);
            }
    }
}

// ---------------------------------------------------------------------------
// Kernel 5: GEMM2 — out[b][k][d] = sum_n St[b][k][n] * Xd[b*Nc+n][d]
// ---------------------------------------------------------------------------
__global__ __launch_bounds__(256, 2) void gemm2_mma(float* __restrict__ out) {
    extern __shared__ __align__(16) char dsm[];
    const int tid = threadIdx.x;
    const int wid = tid >> 5, lane = tid & 31;
    const int d0 = blockIdx.x * 128;
    const int k0 = blockIdx.y * 128;
    const int b  = blockIdx.z;
    const int wm = (wid & 1) * 64;
    const int wn = (wid >> 1) * 32;

    const uint32_t ubase = smem_u32(dsm);
    const int a_r = lane & 15;
    const int a_c = (lane & 16) ? 8 : 0;
    const uint32_t aoff = (uint32_t)((wm + a_r) * TP + a_c) * 2;
    const uint32_t bt4off =
        (uint32_t)(((lane & 7) + ((lane >> 3) & 1) * 8) * BTP + ((lane >> 4) & 1) * 8) * 2;

    const __nv_bfloat16* Sh = g_St_hi + (size_t)b * Kc * Nc;
    const __nv_bfloat16* Sl = g_St_lo + (size_t)b * Kc * Nc;
    const __nv_bfloat16* Xh = g_Xd_hi + (size_t)b * Nc * Dc;
    const __nv_bfloat16* Xl = g_Xd_lo + (size_t)b * Nc * Dc;

    const int lrow = tid >> 2, lv = (tid & 3) * 8;   // A-load mapping
    const int brow = tid >> 4, bseg = tid & 15;      // B-load mapping
    static constexpr int NCH = Nc / 32;   // 32

    float acc[4][4][4] = {};

    auto issue = [&](int c, uint32_t buf) {
        const int nbo = c * 32 + lv;
        #pragma unroll
        for (int i = 0; i < 2; i++) {
            int row = lrow + 64 * i;
            uint32_t so = buf + (uint32_t)(row * TP + lv) * 2;
            cp16(ubase + so,         Sh + (size_t)(k0 + row) * Nc + nbo);
            cp16(ubase + so + TILEB, Sl + (size_t)(k0 + row) * Nc + nbo);
        }
        #pragma unroll
        for (int i = 0; i < 2; i++) {
            int br = brow + 16 * i;
            uint32_t so = buf + 2 * TILEB + (uint32_t)(br * BTP + bseg * 8) * 2;
            size_t gsrc = (size_t)(c * 32 + br) * Dc + d0 + bseg * 8;
            cp16(ubase + so,           Xh + gsrc);
            cp16(ubase + so + B_TILEB, Xl + gsrc);
        }
    };

    issue(0, 0);
    CP_COMMIT();
    for (int c = 0; c < NCH; c++) {
        CP_WAIT0();
        __syncthreads();
        if (c + 1 < NCH) {
            issue(c + 1, (uint32_t)((c + 1) & 1) * BUF2);
            CP_COMMIT();
        }
        mma_chunk2(acc, ubase, (uint32_t)(c & 1) * BUF2, aoff, bt4off, wn);
    }

    float* ob = out + (size_t)b * Kc * Dc;
    #pragma unroll
    for (int mi = 0; mi < 4; mi++) {
        const int kr = k0 + wm + mi * 16 + (lane >> 2);
        #pragma unroll
        for (int ni = 0; ni < 4; ni++) {
            const int dc = d0 + wn + ni * 8 + (lane & 3) * 2;
            float2 o0 = {acc[mi][ni][0], acc[mi][ni][1]};
            float2 o1 = {acc[mi][ni][2], acc[mi][ni][3]};
            *(float2*)(ob + (size_t)kr * Dc + dc) = o0;
            *(float2*)(ob + (size_t)(kr + 8) * Dc + dc) = o1;
        }
    }
}

// ---------------------------------------------------------------------------
extern "C" void kernel_launch(void* const* d_in, const int* in_sizes, int n_in,
                              void* d_out, int out_size) {
    const float* X = (const float*)d_in[0];   // [B,N,D]
    const float* C = (const float*)d_in[1];   // [K,D]
    float* out = (float*)d_out;               // [B,K,D]

    cudaFuncSetAttribute(gemm1_mma, cudaFuncAttributeMaxDynamicSharedMemorySize, SMEM_G1);
    cudaFuncSetAttribute(gemm2_mma, cudaFuncAttributeMaxDynamicSharedMemorySize, SMEM_G2);

    __nv_bfloat16 *xd_h, *xd_l;
    cudaGetSymbolAddress((void**)&xd_h, g_Xd_hi);
    cudaGetSymbolAddress((void**)&xd_l, g_Xd_lo);

    csq_split_kernel<<<Kc, 256>>>(C);                                 // csq + 2C split fused
    split_kernel<<<(int)(((size_t)Mc * Dc / 4) / 256), 256>>>(X, xd_h, xd_l);

    gemm1_mma<<<dim3(Kc / 128, Mc / 128), 256, SMEM_G1>>>();          // (4, 256)

    softmaxT_kernel<<<dim3(Mc / 64, Kc / 64), 256>>>();               // (512, 8)

    gemm2_mma<<<dim3(Dc / 128, Kc / 128, Bc), 256, SMEM_G2>>>(out);   // (6, 4, 32)
}

// round 16
// speedup vs baseline: 1.0098x; 1.0098x over previous
#include <cuda_runtime.h>
#include <cuda_bf16.h>
#include <cstdint>

// ---------------------------------------------------------------------------
// Problem constants
// ---------------------------------------------------------------------------
static constexpr int Bc = 32;
static constexpr int Nc = 1024;
static constexpr int Dc = 768;
static constexpr int Kc = 512;
static constexpr int Mc = Bc * Nc;   // 32768 tokens

// ---------------------------------------------------------------------------
// Global scratch (static __device__ — allocation-guard safe)
// ---------------------------------------------------------------------------
__device__ __align__(16) float         g_L[(size_t)Kc * Mc];      // logits [K][M]
__device__ float                       g_csq[Kc];
__device__ __align__(16) float         g_pmax[(size_t)4 * Mc];    // per-kblock max
__device__ __align__(16) float         g_psum[(size_t)4 * Mc];    // per-kblock sum
__device__ __align__(16) __nv_bfloat16 g_St_hi[(size_t)Bc * Kc * Nc];
__device__ __align__(16) __nv_bfloat16 g_St_lo[(size_t)Bc * Kc * Nc];
__device__ __align__(16) __nv_bfloat16 g_Xd_hi[(size_t)Mc * Dc];
__device__ __align__(16) __nv_bfloat16 g_Xd_lo[(size_t)Mc * Dc];
__device__ __align__(16) __nv_bfloat16 g_C_hi[(size_t)Kc * Dc];   // holds 2*C split
__device__ __align__(16) __nv_bfloat16 g_C_lo[(size_t)Kc * Dc];

// ---------------------------------------------------------------------------
// Primitives (baseline sm_80+ PTX)
// ---------------------------------------------------------------------------
__device__ __forceinline__ uint32_t smem_u32(const void* p) {
    uint32_t a;
    asm("{ .reg .u64 t; cvta.to.shared.u64 t, %1; cvt.u32.u64 %0, t; }" : "=r"(a) : "l"(p));
    return a;
}
__device__ __forceinline__ void ldsm4(uint32_t (&r)[4], uint32_t addr) {
    asm volatile("ldmatrix.sync.aligned.m8n8.x4.shared.b16 {%0,%1,%2,%3}, [%4];"
                 : "=r"(r[0]), "=r"(r[1]), "=r"(r[2]), "=r"(r[3]) : "r"(addr));
}
__device__ __forceinline__ void ldsm4t(uint32_t (&r)[4], uint32_t addr) {
    asm volatile("ldmatrix.sync.aligned.m8n8.x4.trans.shared.b16 {%0,%1,%2,%3}, [%4];"
                 : "=r"(r[0]), "=r"(r[1]), "=r"(r[2]), "=r"(r[3]) : "r"(addr));
}
__device__ __forceinline__ void mma_bf16(float (&d)[4], const uint32_t (&a)[4],
                                         const uint32_t (&b)[2]) {
    asm volatile(
        "mma.sync.aligned.m16n8k16.row.col.f32.bf16.bf16.f32 "
        "{%0,%1,%2,%3}, {%4,%5,%6,%7}, {%8,%9}, {%0,%1,%2,%3};"
        : "+f"(d[0]), "+f"(d[1]), "+f"(d[2]), "+f"(d[3])
        : "r"(a[0]), "r"(a[1]), "r"(a[2]), "r"(a[3]), "r"(b[0]), "r"(b[1]));
}
__device__ __forceinline__ void cp16(uint32_t saddr, const void* g) {
    asm volatile("cp.async.cg.shared.global [%0], [%1], 16;" :: "r"(saddr), "l"(g));
}
#define CP_COMMIT() asm volatile("cp.async.commit_group;" ::: "memory")
#define CP_WAIT0()  asm volatile("cp.async.wait_group 0;" ::: "memory")

// ---------------------------------------------------------------------------
// Tile geometry: CTA 128x128, BK=32, 256 threads (8 warps, 64x32 warp tile),
// 2 stages -> 2 CTAs/SM. Proven best (R14).
// ---------------------------------------------------------------------------
static constexpr int TP = 40;
static constexpr int TILE_ELEMS = 128 * TP;            // 5120
static constexpr int TILEB = TILE_ELEMS * 2;           // 10240 bytes
static constexpr int BUFB  = 4 * TILEB;                // 40960 bytes per stage
static constexpr int SMEM_G1 = 2 * BUFB;               // 81920 bytes

static constexpr int BTP = 136;
static constexpr int B_TILEB = 32 * BTP * 2;           // 8704 bytes
static constexpr int BUF2 = 2 * TILEB + 2 * B_TILEB;   // 37888 bytes per stage
static constexpr int SMEM_G2 = 2 * BUF2;               // 75776 bytes

// ---------------------------------------------------------------------------
// Kernel 1: fused — csq[k] = sum_d C[k,d]^2 AND (2*C) hi/lo bf16 split
// ---------------------------------------------------------------------------
__global__ __launch_bounds__(256) void csq_split_kernel(const float* __restrict__ C) {
    const int k = blockIdx.x, t = threadIdx.x;
    const float* row = C + (size_t)k * Dc;
    __nv_bfloat16* Hr = g_C_hi + (size_t)k * Dc;
    __nv_bfloat16* Lr = g_C_lo + (size_t)k * Dc;
    float s = 0.f;
    #pragma unroll
    for (int i = 0; i < 3; i++) {            // Dc = 768 = 3*256
        int d = t + 256 * i;
        float v = row[d];
        s += v * v;
        float v2 = 2.f * v;                  // fold the 2x into the operand
        __nv_bfloat16 h = __float2bfloat16(v2);
        __nv_bfloat16 l = __float2bfloat16(v2 - __bfloat162float(h));
        Hr[d] = h;
        Lr[d] = l;
    }
    #pragma unroll
    for (int o = 16; o > 0; o >>= 1) s += __shfl_xor_sync(0xffffffffu, s, o);
    __shared__ float red[8];
    if ((t & 31) == 0) red[t >> 5] = s;
    __syncthreads();
    if (t == 0) {
        float tot = 0.f;
        #pragma unroll
        for (int w = 0; w < 8; w++) tot += red[w];
        g_csq[k] = tot;
    }
}

// ---------------------------------------------------------------------------
// Kernel 2: streaming fp32 -> hi/lo bf16 split (X)
// ---------------------------------------------------------------------------
__global__ __launch_bounds__(256) void split_kernel(const float* __restrict__ src,
                                                    __nv_bfloat16* __restrict__ h,
                                                    __nv_bfloat16* __restrict__ l) {
    size_t i = ((size_t)blockIdx.x * 256 + threadIdx.x) * 4;
    float4 v = *(const float4*)(src + i);
    float x[4] = {v.x, v.y, v.z, v.w};
    uint32_t hb[4], lb[4];
    #pragma unroll
    for (int j = 0; j < 4; j++) {
        __nv_bfloat16 hh = __float2bfloat16(x[j]);
        float r = x[j] - __bfloat162float(hh);
        __nv_bfloat16 ll = __float2bfloat16(r);
        hb[j] = (uint32_t)__bfloat16_as_ushort(hh);
        lb[j] = (uint32_t)__bfloat16_as_ushort(ll);
    }
    *(uint2*)(h + i) = make_uint2(hb[0] | (hb[1] << 16), hb[2] | (hb[3] << 16));
    *(uint2*)(l + i) = make_uint2(lb[0] | (lb[1] << 16), lb[2] | (lb[3] << 16));
}

// ---------------------------------------------------------------------------
// GEMM1 MMA phase: A = 2C[k][d], B = Xd[m][d]; B loaded with x4 ldmatrix
// ---------------------------------------------------------------------------
__device__ __forceinline__ void mma_chunk1(float (&acc)[4][4][4], uint32_t ubase,
                                           uint32_t cb, uint32_t aoff, uint32_t b4off) {
    #pragma unroll
    for (int ks = 0; ks < 2; ks++) {
        uint32_t ah[4][4], al[4][4], bh[4][2], bl[4][2];
        #pragma unroll
        for (int mi = 0; mi < 4; mi++) {
            uint32_t off = aoff + (uint32_t)(mi * 16 * TP + ks * 16) * 2;
            ldsm4(ah[mi], ubase + cb + off);
            ldsm4(al[mi], ubase + cb + TILEB + off);
        }
        #pragma unroll
        for (int np = 0; np < 2; np++) {
            uint32_t rh[4], rl[4];
            uint32_t off = b4off + (uint32_t)(np * 16 * TP + ks * 16) * 2;
            ldsm4(rh, ubase + cb + 2 * TILEB + off);
            ldsm4(rl, ubase + cb + 3 * TILEB + off);
            bh[np*2][0] = rh[0]; bh[np*2][1] = rh[1];
            bh[np*2+1][0] = rh[2]; bh[np*2+1][1] = rh[3];
            bl[np*2][0] = rl[0]; bl[np*2][1] = rl[1];
            bl[np*2+1][0] = rl[2]; bl[np*2+1][1] = rl[3];
        }
        #pragma unroll
        for (int mi = 0; mi < 4; mi++)
            #pragma unroll
            for (int ni = 0; ni < 4; ni++) {
                mma_bf16(acc[mi][ni], ah[mi], bh[ni]);
                mma_bf16(acc[mi][ni], ah[mi], bl[ni]);
                mma_bf16(acc[mi][ni], al[mi], bh[ni]);
            }
    }
}

// ---------------------------------------------------------------------------
// Kernel 3: GEMM1 — Lt[k][m] = <2C_k, X_m> - csq[k], + partial softmax stats
// ---------------------------------------------------------------------------
__global__ __launch_bounds__(256, 2) void gemm1_mma() {
    extern __shared__ __align__(16) char dsm[];
    const int tid = threadIdx.x;
    const int wid = tid >> 5, lane = tid & 31;
    const int k0 = blockIdx.x * 128;
    const int m0 = blockIdx.y * 128;
    const int wm = (wid & 1) * 64;
    const int wn = (wid >> 1) * 32;

    const uint32_t ubase = smem_u32(dsm);
    const int a_r = lane & 15;
    const int a_c = (lane & 16) ? 8 : 0;
    const uint32_t aoff = (uint32_t)((wm + a_r) * TP + a_c) * 2;
    const uint32_t b4off =
        (uint32_t)((wn + (lane & 7) + ((lane >> 4) & 1) * 8) * TP + ((lane >> 3) & 1) * 8) * 2;

    const int lrow = tid >> 2, lv = (tid & 3) * 8;
    static constexpr int NCH = Dc / 32;              // 24

    float acc[4][4][4] = {};

    auto issue = [&](int c, uint32_t buf) {
        const int db = c * 32 + lv;
        #pragma unroll
        for (int i = 0; i < 2; i++) {
            int row = lrow + 64 * i;
            uint32_t so = buf + (uint32_t)(row * TP + lv) * 2;
            cp16(ubase + so,             g_C_hi  + (size_t)(k0 + row) * Dc + db);
            cp16(ubase + so + TILEB,     g_C_lo  + (size_t)(k0 + row) * Dc + db);
            cp16(ubase + so + 2 * TILEB, g_Xd_hi + (size_t)(m0 + row) * Dc + db);
            cp16(ubase + so + 3 * TILEB, g_Xd_lo + (size_t)(m0 + row) * Dc + db);
        }
    };

    issue(0, 0);
    CP_COMMIT();
    for (int c = 0; c < NCH; c++) {
        CP_WAIT0();
        __syncthreads();
        if (c + 1 < NCH) {
            issue(c + 1, (uint32_t)((c + 1) & 1) * BUFB);
            CP_COMMIT();
        }
        mma_chunk1(acc, ubase, (uint32_t)(c & 1) * BUFB, aoff, b4off);
    }

    // --- epilogue: logits = acc - csq (2x folded into C) ---
    float cs0v[4], cs1v[4];
    #pragma unroll
    for (int mi = 0; mi < 4; mi++) {
        int kr = k0 + wm + mi * 16 + (lane >> 2);
        cs0v[mi] = g_csq[kr];
        cs1v[mi] = g_csq[kr + 8];
    }
    #pragma unroll
    for (int mi = 0; mi < 4; mi++)
        #pragma unroll
        for (int ni = 0; ni < 4; ni++) {
            acc[mi][ni][0] -= cs0v[mi];
            acc[mi][ni][1] -= cs0v[mi];
            acc[mi][ni][2] -= cs1v[mi];
            acc[mi][ni][3] -= cs1v[mi];
        }
    #pragma unroll
    for (int mi = 0; mi < 4; mi++) {
        const int kr = k0 + wm + mi * 16 + (lane >> 2);
        #pragma unroll
        for (int ni = 0; ni < 4; ni++) {
            const int mc = m0 + wn + ni * 8 + (lane & 3) * 2;
            *(float2*)(g_L + (size_t)kr * Mc + mc) =
                make_float2(acc[mi][ni][0], acc[mi][ni][1]);
            *(float2*)(g_L + (size_t)(kr + 8) * Mc + mc) =
                make_float2(acc[mi][ni][2], acc[mi][ni][3]);
        }
    }

    // --- partial softmax stats over this CTA's 128 k-rows ---
    __syncthreads();
    float* pm2 = (float*)dsm;            // [2][128]
    float* ps2 = pm2 + 256;              // [2][128]
    #pragma unroll
    for (int ni = 0; ni < 4; ni++) {
        float m0v = -3.4e38f, m1v = -3.4e38f;
        #pragma unroll
        for (int mi = 0; mi < 4; mi++) {
            m0v = fmaxf(m0v, fmaxf(acc[mi][ni][0], acc[mi][ni][2]));
            m1v = fmaxf(m1v, fmaxf(acc[mi][ni][1], acc[mi][ni][3]));
        }
        #pragma unroll
        for (int o = 4; o <= 16; o <<= 1) {
            m0v = fmaxf(m0v, __shfl_xor_sync(0xffffffffu, m0v, o));
            m1v = fmaxf(m1v, __shfl_xor_sync(0xffffffffu, m1v, o));
        }
        float s0 = 0.f, s1 = 0.f;
        #pragma unroll
        for (int mi = 0; mi < 4; mi++) {
            s0 += __expf(acc[mi][ni][0] - m0v) + __expf(acc[mi][ni][2] - m0v);
            s1 += __expf(acc[mi][ni][1] - m1v) + __expf(acc[mi][ni][3] - m1v);
        }
        #pragma unroll
        for (int o = 4; o <= 16; o <<= 1) {
            s0 += __shfl_xor_sync(0xffffffffu, s0, o);
            s1 += __shfl_xor_sync(0xffffffffu, s1, o);
        }
        if ((lane >> 2) == 0) {
            int col = wn + ni * 8 + (lane & 3) * 2;
            int h = (wid & 1) * 128;
            pm2[h + col]     = m0v;  ps2[h + col]     = s0;
            pm2[h + col + 1] = m1v;  ps2[h + col + 1] = s1;
        }
    }
    __syncthreads();
    if (tid < 128) {
        float Ma = pm2[tid], Mb = pm2[128 + tid];
        float M = fmaxf(Ma, Mb);
        float S = ps2[tid] * __expf(Ma - M) + ps2[128 + tid] * __expf(Mb - M);
        g_pmax[(size_t)blockIdx.x * Mc + m0 + tid] = M;
        g_psum[(size_t)blockIdx.x * Mc + m0 + tid] = S;
    }
}

// ---------------------------------------------------------------------------
// Kernel 4: softmax apply — float4 lanes (4 cols each), k-split over grid.y.
// Block: 128 token-columns (32 lanes x 4), 8 warps x 8 k-rows.
// Grid: (Mc/128, Kc/64) = (256, 8).
// ---------------------------------------------------------------------------
__global__ __launch_bounds__(256) void softmaxT_kernel() {
    const int lane = threadIdx.x & 31;
    const int warp = threadIdx.x >> 5;               // 0..7
    const int m0 = blockIdx.x * 128 + lane * 4;      // 4 columns per lane
    const int b  = m0 >> 10;
    const int n0 = m0 & 1023;
    const int kb = blockIdx.y * 64 + warp * 8;

    // combine 4 partial stats for these 4 columns (float4 loads)
    float gm[4] = {-3.4e38f, -3.4e38f, -3.4e38f, -3.4e38f};
    float gs[4] = {0.f, 0.f, 0.f, 0.f};
    #pragma unroll
    for (int p = 0; p < 4; p++) {
        float4 pM = *(const float4*)(g_pmax + (size_t)p * Mc + m0);
        float4 pS = *(const float4*)(g_psum + (size_t)p * Mc + m0);
        float pm[4] = {pM.x, pM.y, pM.z, pM.w};
        float ps[4] = {pS.x, pS.y, pS.z, pS.w};
        #pragma unroll
        for (int j = 0; j < 4; j++) {
            float nm = fmaxf(gm[j], pm[j]);
            gs[j] = gs[j] * __expf(gm[j] - nm) + ps[j] * __expf(pm[j] - nm);
            gm[j] = nm;
        }
    }
    float inv[4];
    #pragma unroll
    for (int j = 0; j < 4; j++) inv[j] = 1.0f / gs[j];

    __nv_bfloat16* SH = g_St_hi + (size_t)b * Kc * Nc + n0;
    __nv_bfloat16* SL = g_St_lo + (size_t)b * Kc * Nc + n0;
    #pragma unroll
    for (int k = kb; k < kb + 8; k++) {
        float4 v4 = *(const float4*)(g_L + (size_t)k * Mc + m0);
        float v[4] = {v4.x, v4.y, v4.z, v4.w};
        uint32_t hb[4], lb[4];
        #pragma unroll
        for (int j = 0; j < 4; j++) {
            float p = __expf(v[j] - gm[j]) * inv[j];
            __nv_bfloat16 h = __float2bfloat16(p);
            __nv_bfloat16 l = __float2bfloat16(p - __bfloat162float(h));
            hb[j] = (uint32_t)__bfloat16_as_ushort(h);
            lb[j] = (uint32_t)__bfloat16_as_ushort(l);
        }
        *(uint2*)(SH + (size_t)k * Nc) =
            make_uint2(hb[0] | (hb[1] << 16), hb[2] | (hb[3] << 16));
        *(uint2*)(SL + (size_t)k * Nc) =
            make_uint2(lb[0] | (lb[1] << 16), lb[2] | (lb[3] << 16));
    }
}

// ---------------------------------------------------------------------------
// GEMM2 MMA phase: A = St [k][n] (non-trans), B = Xd [n][d] via x4 TRANS ldsm
// ---------------------------------------------------------------------------
__device__ __forceinline__ void mma_chunk2(float (&acc)[4][4][4], uint32_t ubase,
                                           uint32_t cb, uint32_t aoff,
                                           uint32_t bt4off, int wn) {
    #pragma unroll
    for (int ks = 0; ks < 2; ks++) {
        uint32_t ah[4][4], al[4][4], bh[4][2], bl[4][2];
        #pragma unroll
        for (int mi = 0; mi < 4; mi++) {
            uint32_t off = aoff + (uint32_t)(mi * 16 * TP + ks * 16) * 2;
            ldsm4(ah[mi], ubase + cb + off);
            ldsm4(al[mi], ubase + cb + TILEB + off);
        }
        #pragma unroll
        for (int np = 0; np < 2; np++) {
            uint32_t rh[4], rl[4];
            uint32_t off = bt4off + (uint32_t)(ks * 16 * BTP + wn + np * 16) * 2;
            ldsm4t(rh, ubase + cb + 2 * TILEB + off);
            ldsm4t(rl, ubase + cb + 2 * TILEB + B_TILEB + off);
            bh[np*2][0] = rh[0]; bh[np*2][1] = rh[1];
            bh[np*2+1][0] = rh[2]; bh[np*2+1][1] = rh[3];
            bl[np*2][0] = rl[0]; bl[np*2][1] = rl[1];
            bl[np*2+1][0] = rl[2]; bl[np*2+1][1] = rl[3];
        }
        #pragma unroll
        for (int mi = 0; mi < 4; mi++)
            #pragma unroll
            for (int ni = 0; ni < 4; ni++) {
                mma_bf16(acc[mi][ni], ah[mi], bh[ni]);
                mma_bf16(acc[mi][ni], ah[mi], bl[ni]);
                mma_bf16(acc[mi][ni], al[mi], bh[ni]);
            }
    }
}

// ---------------------------------------------------------------------------
// Kernel 5: GEMM2 — out[b][k][d] = sum_n St[b][k][n] * Xd[b*Nc+n][d]
// ---------------------------------------------------------------------------
__global__ __launch_bounds__(256, 2) void gemm2_mma(float* __restrict__ out) {
    extern __shared__ __align__(16) char dsm[];
    const int tid = threadIdx.x;
    const int wid = tid >> 5, lane = tid & 31;
    const int d0 = blockIdx.x * 128;
    const int k0 = blockIdx.y * 128;
    const int b  = blockIdx.z;
    const int wm = (wid & 1) * 64;
    const int wn = (wid >> 1) * 32;

    const uint32_t ubase = smem_u32(dsm);
    const int a_r = lane & 15;
    const int a_c = (lane & 16) ? 8 : 0;
    const uint32_t aoff = (uint32_t)((wm + a_r) * TP + a_c) * 2;
    const uint32_t bt4off =
        (uint32_t)(((lane & 7) + ((lane >> 3) & 1) * 8) * BTP + ((lane >> 4) & 1) * 8) * 2;

    const __nv_bfloat16* Sh = g_St_hi + (size_t)b * Kc * Nc;
    const __nv_bfloat16* Sl = g_St_lo + (size_t)b * Kc * Nc;
    const __nv_bfloat16* Xh = g_Xd_hi + (size_t)b * Nc * Dc;
    const __nv_bfloat16* Xl = g_Xd_lo + (size_t)b * Nc * Dc;

    const int lrow = tid >> 2, lv = (tid & 3) * 8;   // A-load mapping
    const int brow = tid >> 4, bseg = tid & 15;      // B-load mapping
    static constexpr int NCH = Nc / 32;   // 32

    float acc[4][4][4] = {};

    auto issue = [&](int c, uint32_t buf) {
        const int nbo = c * 32 + lv;
        #pragma unroll
        for (int i = 0; i < 2; i++) {
            int row = lrow + 64 * i;
            uint32_t so = buf + (uint32_t)(row * TP + lv) * 2;
            cp16(ubase + so,         Sh + (size_t)(k0 + row) * Nc + nbo);
            cp16(ubase + so + TILEB, Sl + (size_t)(k0 + row) * Nc + nbo);
        }
        #pragma unroll
        for (int i = 0; i < 2; i++) {
            int br = brow + 16 * i;
            uint32_t so = buf + 2 * TILEB + (uint32_t)(br * BTP + bseg * 8) * 2;
            size_t gsrc = (size_t)(c * 32 + br) * Dc + d0 + bseg * 8;
            cp16(ubase + so,           Xh + gsrc);
            cp16(ubase + so + B_TILEB, Xl + gsrc);
        }
    };

    issue(0, 0);
    CP_COMMIT();
    for (int c = 0; c < NCH; c++) {
        CP_WAIT0();
        __syncthreads();
        if (c + 1 < NCH) {
            issue(c + 1, (uint32_t)((c + 1) & 1) * BUF2);
            CP_COMMIT();
        }
        mma_chunk2(acc, ubase, (uint32_t)(c & 1) * BUF2, aoff, bt4off, wn);
    }

    float* ob = out + (size_t)b * Kc * Dc;
    #pragma unroll
    for (int mi = 0; mi < 4; mi++) {
        const int kr = k0 + wm + mi * 16 + (lane >> 2);
        #pragma unroll
        for (int ni = 0; ni < 4; ni++) {
            const int dc = d0 + wn + ni * 8 + (lane & 3) * 2;
            float2 o0 = {acc[mi][ni][0], acc[mi][ni][1]};
            float2 o1 = {acc[mi][ni][2], acc[mi][ni][3]};
            *(float2*)(ob + (size_t)kr * Dc + dc) = o0;
            *(float2*)(ob + (size_t)(kr + 8) * Dc + dc) = o1;
        }
    }
}

// ---------------------------------------------------------------------------
extern "C" void kernel_launch(void* const* d_in, const int* in_sizes, int n_in,
                              void* d_out, int out_size) {
    const float* X = (const float*)d_in[0];   // [B,N,D]
    const float* C = (const float*)d_in[1];   // [K,D]
    float* out = (float*)d_out;               // [B,K,D]

    cudaFuncSetAttribute(gemm1_mma, cudaFuncAttributeMaxDynamicSharedMemorySize, SMEM_G1);
    cudaFuncSetAttribute(gemm2_mma, cudaFuncAttributeMaxDynamicSharedMemorySize, SMEM_G2);

    __nv_bfloat16 *xd_h, *xd_l;
    cudaGetSymbolAddress((void**)&xd_h, g_Xd_hi);
    cudaGetSymbolAddress((void**)&xd_l, g_Xd_lo);

    csq_split_kernel<<<Kc, 256>>>(C);                                 // csq + 2C split fused
    split_kernel<<<(int)(((size_t)Mc * Dc / 4) / 256), 256>>>(X, xd_h, xd_l);

    gemm1_mma<<<dim3(Kc / 128, Mc / 128), 256, SMEM_G1>>>();          // (4, 256)

    softmaxT_kernel<<<dim3(Mc / 128, Kc / 64), 256>>>();              // (256, 8)

    gemm2_mma<<<dim3(Dc / 128, Kc / 128, Bc), 256, SMEM_G2>>>(out);   // (6, 4, 32)
}

// round 17
// speedup vs baseline: 1.0182x; 1.0084x over previous
#include <cuda_runtime.h>
#include <cuda_bf16.h>
#include <cstdint>

// ---------------------------------------------------------------------------
// Problem constants
// ---------------------------------------------------------------------------
static constexpr int Bc = 32;
static constexpr int Nc = 1024;
static constexpr int Dc = 768;
static constexpr int Kc = 512;
static constexpr int Mc = Bc * Nc;   // 32768 tokens

// ---------------------------------------------------------------------------
// Global scratch (static __device__ — allocation-guard safe)
// ---------------------------------------------------------------------------
__device__ __align__(16) float         g_L[(size_t)Kc * Mc];      // logits [K][M]
__device__ float                       g_csq[Kc];
__device__ __align__(16) float         g_pmax[(size_t)4 * Mc];    // per-kblock max
__device__ __align__(16) float         g_psum[(size_t)4 * Mc];    // per-kblock sum
__device__ __align__(16) __nv_bfloat16 g_St_hi[(size_t)Bc * Kc * Nc];
__device__ __align__(16) __nv_bfloat16 g_St_lo[(size_t)Bc * Kc * Nc];
__device__ __align__(16) __nv_bfloat16 g_Xd_hi[(size_t)Mc * Dc];
__device__ __align__(16) __nv_bfloat16 g_Xd_lo[(size_t)Mc * Dc];
__device__ __align__(16) __nv_bfloat16 g_C_hi[(size_t)Kc * Dc];   // holds 2*C split
__device__ __align__(16) __nv_bfloat16 g_C_lo[(size_t)Kc * Dc];

// ---------------------------------------------------------------------------
// Primitives (baseline sm_80+ PTX)
// ---------------------------------------------------------------------------
__device__ __forceinline__ uint32_t smem_u32(const void* p) {
    uint32_t a;
    asm("{ .reg .u64 t; cvta.to.shared.u64 t, %1; cvt.u32.u64 %0, t; }" : "=r"(a) : "l"(p));
    return a;
}
__device__ __forceinline__ void ldsm4(uint32_t (&r)[4], uint32_t addr) {
    asm volatile("ldmatrix.sync.aligned.m8n8.x4.shared.b16 {%0,%1,%2,%3}, [%4];"
                 : "=r"(r[0]), "=r"(r[1]), "=r"(r[2]), "=r"(r[3]) : "r"(addr));
}
__device__ __forceinline__ void ldsm4t(uint32_t (&r)[4], uint32_t addr) {
    asm volatile("ldmatrix.sync.aligned.m8n8.x4.trans.shared.b16 {%0,%1,%2,%3}, [%4];"
                 : "=r"(r[0]), "=r"(r[1]), "=r"(r[2]), "=r"(r[3]) : "r"(addr));
}
__device__ __forceinline__ void mma_bf16(float (&d)[4], const uint32_t (&a)[4],
                                         const uint32_t (&b)[2]) {
    asm volatile(
        "mma.sync.aligned.m16n8k16.row.col.f32.bf16.bf16.f32 "
        "{%0,%1,%2,%3}, {%4,%5,%6,%7}, {%8,%9}, {%0,%1,%2,%3};"
        : "+f"(d[0]), "+f"(d[1]), "+f"(d[2]), "+f"(d[3])
        : "r"(a[0]), "r"(a[1]), "r"(a[2]), "r"(a[3]), "r"(b[0]), "r"(b[1]));
}
__device__ __forceinline__ void cp16(uint32_t saddr, const void* g) {
    asm volatile("cp.async.cg.shared.global [%0], [%1], 16;" :: "r"(saddr), "l"(g));
}
#define CP_COMMIT() asm volatile("cp.async.commit_group;" ::: "memory")
#define CP_WAIT0()  asm volatile("cp.async.wait_group 0;" ::: "memory")

// ---------------------------------------------------------------------------
// Tile geometry: CTA 128x128, BK=32, 256 threads (8 warps, 64x32 warp tile),
// 2 stages -> 2 CTAs/SM. Proven best (R14/R16).
// ---------------------------------------------------------------------------
static constexpr int TP = 40;
static constexpr int TILE_ELEMS = 128 * TP;            // 5120
static constexpr int TILEB = TILE_ELEMS * 2;           // 10240 bytes
static constexpr int BUFB  = 4 * TILEB;                // 40960 bytes per stage
static constexpr int SMEM_G1 = 2 * BUFB;               // 81920 bytes

static constexpr int BTP = 136;
static constexpr int B_TILEB = 32 * BTP * 2;           // 8704 bytes
static constexpr int BUF2 = 2 * TILEB + 2 * B_TILEB;   // 37888 bytes per stage
static constexpr int SMEM_G2 = 2 * BUF2;               // 75776 bytes

// ---------------------------------------------------------------------------
// Kernel 1: MERGED prep — blocks [0,Kc): csq + (2C) hi/lo split (one C row);
//                          blocks [Kc,..): X hi/lo split (1024-elem chunk).
// ---------------------------------------------------------------------------
static constexpr int PREP_XBLK = (int)(((size_t)Mc * Dc / 4) / 256);  // 24576
__global__ __launch_bounds__(256) void prep_kernel(const float* __restrict__ C,
                                                   const float* __restrict__ X) {
    const int t = threadIdx.x;
    if (blockIdx.x < (unsigned)Kc) {
        // --- C path: csq + folded-2x split ---
        const int k = blockIdx.x;
        const float* row = C + (size_t)k * Dc;
        __nv_bfloat16* Hr = g_C_hi + (size_t)k * Dc;
        __nv_bfloat16* Lr = g_C_lo + (size_t)k * Dc;
        float s = 0.f;
        #pragma unroll
        for (int i = 0; i < 3; i++) {            // Dc = 768 = 3*256
            int d = t + 256 * i;
            float v = row[d];
            s += v * v;
            float v2 = 2.f * v;
            __nv_bfloat16 h = __float2bfloat16(v2);
            __nv_bfloat16 l = __float2bfloat16(v2 - __bfloat162float(h));
            Hr[d] = h;
            Lr[d] = l;
        }
        #pragma unroll
        for (int o = 16; o > 0; o >>= 1) s += __shfl_xor_sync(0xffffffffu, s, o);
        __shared__ float red[8];
        if ((t & 31) == 0) red[t >> 5] = s;
        __syncthreads();
        if (t == 0) {
            float tot = 0.f;
            #pragma unroll
            for (int w = 0; w < 8; w++) tot += red[w];
            g_csq[k] = tot;
        }
    } else {
        // --- X path: streaming hi/lo split, float4 per thread ---
        size_t i = ((size_t)(blockIdx.x - Kc) * 256 + t) * 4;
        float4 v = *(const float4*)(X + i);
        float x[4] = {v.x, v.y, v.z, v.w};
        uint32_t hb[4], lb[4];
        #pragma unroll
        for (int j = 0; j < 4; j++) {
            __nv_bfloat16 hh = __float2bfloat16(x[j]);
            float r = x[j] - __bfloat162float(hh);
            __nv_bfloat16 ll = __float2bfloat16(r);
            hb[j] = (uint32_t)__bfloat16_as_ushort(hh);
            lb[j] = (uint32_t)__bfloat16_as_ushort(ll);
        }
        *(uint2*)(g_Xd_hi + i) = make_uint2(hb[0] | (hb[1] << 16), hb[2] | (hb[3] << 16));
        *(uint2*)(g_Xd_lo + i) = make_uint2(lb[0] | (lb[1] << 16), lb[2] | (lb[3] << 16));
    }
}

// ---------------------------------------------------------------------------
// GEMM1 MMA phase: A = 2C[k][d], B = Xd[m][d]; B loaded with x4 ldmatrix
// ---------------------------------------------------------------------------
__device__ __forceinline__ void mma_chunk1(float (&acc)[4][4][4], uint32_t ubase,
                                           uint32_t cb, uint32_t aoff, uint32_t b4off) {
    #pragma unroll
    for (int ks = 0; ks < 2; ks++) {
        uint32_t ah[4][4], al[4][4], bh[4][2], bl[4][2];
        #pragma unroll
        for (int mi = 0; mi < 4; mi++) {
            uint32_t off = aoff + (uint32_t)(mi * 16 * TP + ks * 16) * 2;
            ldsm4(ah[mi], ubase + cb + off);
            ldsm4(al[mi], ubase + cb + TILEB + off);
        }
        #pragma unroll
        for (int np = 0; np < 2; np++) {
            uint32_t rh[4], rl[4];
            uint32_t off = b4off + (uint32_t)(np * 16 * TP + ks * 16) * 2;
            ldsm4(rh, ubase + cb + 2 * TILEB + off);
            ldsm4(rl, ubase + cb + 3 * TILEB + off);
            bh[np*2][0] = rh[0]; bh[np*2][1] = rh[1];
            bh[np*2+1][0] = rh[2]; bh[np*2+1][1] = rh[3];
            bl[np*2][0] = rl[0]; bl[np*2][1] = rl[1];
            bl[np*2+1][0] = rl[2]; bl[np*2+1][1] = rl[3];
        }
        #pragma unroll
        for (int mi = 0; mi < 4; mi++)
            #pragma unroll
            for (int ni = 0; ni < 4; ni++) {
                mma_bf16(acc[mi][ni], ah[mi], bh[ni]);
                mma_bf16(acc[mi][ni], ah[mi], bl[ni]);
                mma_bf16(acc[mi][ni], al[mi], bh[ni]);
            }
    }
}

// ---------------------------------------------------------------------------
// Kernel 2: GEMM1 — Lt[k][m] = <2C_k, X_m> - csq[k], + partial softmax stats
// ---------------------------------------------------------------------------
__global__ __launch_bounds__(256, 2) void gemm1_mma() {
    extern __shared__ __align__(16) char dsm[];
    const int tid = threadIdx.x;
    const int wid = tid >> 5, lane = tid & 31;
    const int k0 = blockIdx.x * 128;
    const int m0 = blockIdx.y * 128;
    const int wm = (wid & 1) * 64;
    const int wn = (wid >> 1) * 32;

    const uint32_t ubase = smem_u32(dsm);
    const int a_r = lane & 15;
    const int a_c = (lane & 16) ? 8 : 0;
    const uint32_t aoff = (uint32_t)((wm + a_r) * TP + a_c) * 2;
    const uint32_t b4off =
        (uint32_t)((wn + (lane & 7) + ((lane >> 4) & 1) * 8) * TP + ((lane >> 3) & 1) * 8) * 2;

    const int lrow = tid >> 2, lv = (tid & 3) * 8;
    static constexpr int NCH = Dc / 32;              // 24

    float acc[4][4][4] = {};

    auto issue = [&](int c, uint32_t buf) {
        const int db = c * 32 + lv;
        #pragma unroll
        for (int i = 0; i < 2; i++) {
            int row = lrow + 64 * i;
            uint32_t so = buf + (uint32_t)(row * TP + lv) * 2;
            cp16(ubase + so,             g_C_hi  + (size_t)(k0 + row) * Dc + db);
            cp16(ubase + so + TILEB,     g_C_lo  + (size_t)(k0 + row) * Dc + db);
            cp16(ubase + so + 2 * TILEB, g_Xd_hi + (size_t)(m0 + row) * Dc + db);
            cp16(ubase + so + 3 * TILEB, g_Xd_lo + (size_t)(m0 + row) * Dc + db);
        }
    };

    issue(0, 0);
    CP_COMMIT();
    for (int c = 0; c < NCH; c++) {
        CP_WAIT0();
        __syncthreads();
        if (c + 1 < NCH) {
            issue(c + 1, (uint32_t)((c + 1) & 1) * BUFB);
            CP_COMMIT();
        }
        mma_chunk1(acc, ubase, (uint32_t)(c & 1) * BUFB, aoff, b4off);
    }

    // --- epilogue: logits = acc - csq (2x folded into C) ---
    float cs0v[4], cs1v[4];
    #pragma unroll
    for (int mi = 0; mi < 4; mi++) {
        int kr = k0 + wm + mi * 16 + (lane >> 2);
        cs0v[mi] = g_csq[kr];
        cs1v[mi] = g_csq[kr + 8];
    }
    #pragma unroll
    for (int mi = 0; mi < 4; mi++)
        #pragma unroll
        for (int ni = 0; ni < 4; ni++) {
            acc[mi][ni][0] -= cs0v[mi];
            acc[mi][ni][1] -= cs0v[mi];
            acc[mi][ni][2] -= cs1v[mi];
            acc[mi][ni][3] -= cs1v[mi];
        }
    #pragma unroll
    for (int mi = 0; mi < 4; mi++) {
        const int kr = k0 + wm + mi * 16 + (lane >> 2);
        #pragma unroll
        for (int ni = 0; ni < 4; ni++) {
            const int mc = m0 + wn + ni * 8 + (lane & 3) * 2;
            *(float2*)(g_L + (size_t)kr * Mc + mc) =
                make_float2(acc[mi][ni][0], acc[mi][ni][1]);
            *(float2*)(g_L + (size_t)(kr + 8) * Mc + mc) =
                make_float2(acc[mi][ni][2], acc[mi][ni][3]);
        }
    }

    // --- partial softmax stats over this CTA's 128 k-rows ---
    __syncthreads();
    float* pm2 = (float*)dsm;            // [2][128]
    float* ps2 = pm2 + 256;              // [2][128]
    #pragma unroll
    for (int ni = 0; ni < 4; ni++) {
        float m0v = -3.4e38f, m1v = -3.4e38f;
        #pragma unroll
        for (int mi = 0; mi < 4; mi++) {
            m0v = fmaxf(m0v, fmaxf(acc[mi][ni][0], acc[mi][ni][2]));
            m1v = fmaxf(m1v, fmaxf(acc[mi][ni][1], acc[mi][ni][3]));
        }
        #pragma unroll
        for (int o = 4; o <= 16; o <<= 1) {
            m0v = fmaxf(m0v, __shfl_xor_sync(0xffffffffu, m0v, o));
            m1v = fmaxf(m1v, __shfl_xor_sync(0xffffffffu, m1v, o));
        }
        float s0 = 0.f, s1 = 0.f;
        #pragma unroll
        for (int mi = 0; mi < 4; mi++) {
            s0 += __expf(acc[mi][ni][0] - m0v) + __expf(acc[mi][ni][2] - m0v);
            s1 += __expf(acc[mi][ni][1] - m1v) + __expf(acc[mi][ni][3] - m1v);
        }
        #pragma unroll
        for (int o = 4; o <= 16; o <<= 1) {
            s0 += __shfl_xor_sync(0xffffffffu, s0, o);
            s1 += __shfl_xor_sync(0xffffffffu, s1, o);
        }
        if ((lane >> 2) == 0) {
            int col = wn + ni * 8 + (lane & 3) * 2;
            int h = (wid & 1) * 128;
            pm2[h + col]     = m0v;  ps2[h + col]     = s0;
            pm2[h + col + 1] = m1v;  ps2[h + col + 1] = s1;
        }
    }
    __syncthreads();
    if (tid < 128) {
        float Ma = pm2[tid], Mb = pm2[128 + tid];
        float M = fmaxf(Ma, Mb);
        float S = ps2[tid] * __expf(Ma - M) + ps2[128 + tid] * __expf(Mb - M);
        g_pmax[(size_t)blockIdx.x * Mc + m0 + tid] = M;
        g_psum[(size_t)blockIdx.x * Mc + m0 + tid] = S;
    }
}

// ---------------------------------------------------------------------------
// Kernel 3: softmax apply — float4 lanes (4 cols each), k-split over grid.y.
// ---------------------------------------------------------------------------
__global__ __launch_bounds__(256) void softmaxT_kernel() {
    const int lane = threadIdx.x & 31;
    const int warp = threadIdx.x >> 5;               // 0..7
    const int m0 = blockIdx.x * 128 + lane * 4;      // 4 columns per lane
    const int b  = m0 >> 10;
    const int n0 = m0 & 1023;
    const int kb = blockIdx.y * 64 + warp * 8;

    float gm[4] = {-3.4e38f, -3.4e38f, -3.4e38f, -3.4e38f};
    float gs[4] = {0.f, 0.f, 0.f, 0.f};
    #pragma unroll
    for (int p = 0; p < 4; p++) {
        float4 pM = *(const float4*)(g_pmax + (size_t)p * Mc + m0);
        float4 pS = *(const float4*)(g_psum + (size_t)p * Mc + m0);
        float pm[4] = {pM.x, pM.y, pM.z, pM.w};
        float ps[4] = {pS.x, pS.y, pS.z, pS.w};
        #pragma unroll
        for (int j = 0; j < 4; j++) {
            float nm = fmaxf(gm[j], pm[j]);
            gs[j] = gs[j] * __expf(gm[j] - nm) + ps[j] * __expf(pm[j] - nm);
            gm[j] = nm;
        }
    }
    float inv[4];
    #pragma unroll
    for (int j = 0; j < 4; j++) inv[j] = 1.0f / gs[j];

    __nv_bfloat16* SH = g_St_hi + (size_t)b * Kc * Nc + n0;
    __nv_bfloat16* SL = g_St_lo + (size_t)b * Kc * Nc + n0;
    #pragma unroll
    for (int k = kb; k < kb + 8; k++) {
        float4 v4 = *(const float4*)(g_L + (size_t)k * Mc + m0);
        float v[4] = {v4.x, v4.y, v4.z, v4.w};
        uint32_t hb[4], lb[4];
        #pragma unroll
        for (int j = 0; j < 4; j++) {
            float p = __expf(v[j] - gm[j]) * inv[j];
            __nv_bfloat16 h = __float2bfloat16(p);
            __nv_bfloat16 l = __float2bfloat16(p - __bfloat162float(h));
            hb[j] = (uint32_t)__bfloat16_as_ushort(h);
            lb[j] = (uint32_t)__bfloat16_as_ushort(l);
        }
        *(uint2*)(SH + (size_t)k * Nc) =
            make_uint2(hb[0] | (hb[1] << 16), hb[2] | (hb[3] << 16));
        *(uint2*)(SL + (size_t)k * Nc) =
            make_uint2(lb[0] | (lb[1] << 16), lb[2] | (lb[3] << 16));
    }
}

// ---------------------------------------------------------------------------
// GEMM2 MMA phase: A = St [k][n] (non-trans), B = Xd [n][d] via x4 TRANS ldsm
// ---------------------------------------------------------------------------
__device__ __forceinline__ void mma_chunk2(float (&acc)[4][4][4], uint32_t ubase,
                                           uint32_t cb, uint32_t aoff,
                                           uint32_t bt4off, int wn) {
    #pragma unroll
    for (int ks = 0; ks < 2; ks++) {
        uint32_t ah[4][4], al[4][4], bh[4][2], bl[4][2];
        #pragma unroll
        for (int mi = 0; mi < 4; mi++) {
            uint32_t off = aoff + (uint32_t)(mi * 16 * TP + ks * 16) * 2;
            ldsm4(ah[mi], ubase + cb + off);
            ldsm4(al[mi], ubase + cb + TILEB + off);
        }
        #pragma unroll
        for (int np = 0; np < 2; np++) {
            uint32_t rh[4], rl[4];
            uint32_t off = bt4off + (uint32_t)(ks * 16 * BTP + wn + np * 16) * 2;
            ldsm4t(rh, ubase + cb + 2 * TILEB + off);
            ldsm4t(rl, ubase + cb + 2 * TILEB + B_TILEB + off);
            bh[np*2][0] = rh[0]; bh[np*2][1] = rh[1];
            bh[np*2+1][0] = rh[2]; bh[np*2+1][1] = rh[3];
            bl[np*2][0] = rl[0]; bl[np*2][1] = rl[1];
            bl[np*2+1][0] = rl[2]; bl[np*2+1][1] = rl[3];
        }
        #pragma unroll
        for (int mi = 0; mi < 4; mi++)
            #pragma unroll
            for (int ni = 0; ni < 4; ni++) {
                mma_bf16(acc[mi][ni], ah[mi], bh[ni]);
                mma_bf16(acc[mi][ni], ah[mi], bl[ni]);
                mma_bf16(acc[mi][ni], al[mi], bh[ni]);
            }
    }
}

// ---------------------------------------------------------------------------
// Kernel 4: GEMM2 — out[b][k][d] = sum_n St[b][k][n] * Xd[b*Nc+n][d]
// ---------------------------------------------------------------------------
__global__ __launch_bounds__(256, 2) void gemm2_mma(float* __restrict__ out) {
    extern __shared__ __align__(16) char dsm[];
    const int tid = threadIdx.x;
    const int wid = tid >> 5, lane = tid & 31;
    const int d0 = blockIdx.x * 128;
    const int k0 = blockIdx.y * 128;
    const int b  = blockIdx.z;
    const int wm = (wid & 1) * 64;
    const int wn = (wid >> 1) * 32;

    const uint32_t ubase = smem_u32(dsm);
    const int a_r = lane & 15;
    const int a_c = (lane & 16) ? 8 : 0;
    const uint32_t aoff = (uint32_t)((wm + a_r) * TP + a_c) * 2;
    const uint32_t bt4off =
        (uint32_t)(((lane & 7) + ((lane >> 3) & 1) * 8) * BTP + ((lane >> 4) & 1) * 8) * 2;

    const __nv_bfloat16* Sh = g_St_hi + (size_t)b * Kc * Nc;
    const __nv_bfloat16* Sl = g_St_lo + (size_t)b * Kc * Nc;
    const __nv_bfloat16* Xh = g_Xd_hi + (size_t)b * Nc * Dc;
    const __nv_bfloat16* Xl = g_Xd_lo + (size_t)b * Nc * Dc;

    const int lrow = tid >> 2, lv = (tid & 3) * 8;   // A-load mapping
    const int brow = tid >> 4, bseg = tid & 15;      // B-load mapping
    static constexpr int NCH = Nc / 32;   // 32

    float acc[4][4][4] = {};

    auto issue = [&](int c, uint32_t buf) {
        const int nbo = c * 32 + lv;
        #pragma unroll
        for (int i = 0; i < 2; i++) {
            int row = lrow + 64 * i;
            uint32_t so = buf + (uint32_t)(row * TP + lv) * 2;
            cp16(ubase + so,         Sh + (size_t)(k0 + row) * Nc + nbo);
            cp16(ubase + so + TILEB, Sl + (size_t)(k0 + row) * Nc + nbo);
        }
        #pragma unroll
        for (int i = 0; i < 2; i++) {
            int br = brow + 16 * i;
            uint32_t so = buf + 2 * TILEB + (uint32_t)(br * BTP + bseg * 8) * 2;
            size_t gsrc = (size_t)(c * 32 + br) * Dc + d0 + bseg * 8;
            cp16(ubase + so,           Xh + gsrc);
            cp16(ubase + so + B_TILEB, Xl + gsrc);
        }
    };

    issue(0, 0);
    CP_COMMIT();
    for (int c = 0; c < NCH; c++) {
        CP_WAIT0();
        __syncthreads();
        if (c + 1 < NCH) {
            issue(c + 1, (uint32_t)((c + 1) & 1) * BUF2);
            CP_COMMIT();
        }
        mma_chunk2(acc, ubase, (uint32_t)(c & 1) * BUF2, aoff, bt4off, wn);
    }

    float* ob = out + (size_t)b * Kc * Dc;
    #pragma unroll
    for (int mi = 0; mi < 4; mi++) {
        const int kr = k0 + wm + mi * 16 + (lane >> 2);
        #pragma unroll
        for (int ni = 0; ni < 4; ni++) {
            const int dc = d0 + wn + ni * 8 + (lane & 3) * 2;
            float2 o0 = {acc[mi][ni][0], acc[mi][ni][1]};
            float2 o1 = {acc[mi][ni][2], acc[mi][ni][3]};
            *(float2*)(ob + (size_t)kr * Dc + dc) = o0;
            *(float2*)(ob + (size_t)(kr + 8) * Dc + dc) = o1;
        }
    }
}

// ---------------------------------------------------------------------------
extern "C" void kernel_launch(void* const* d_in, const int* in_sizes, int n_in,
                              void* d_out, int out_size) {
    const float* X = (const float*)d_in[0];   // [B,N,D]
    const float* C = (const float*)d_in[1];   // [K,D]
    float* out = (float*)d_out;               // [B,K,D]

    cudaFuncSetAttribute(gemm1_mma, cudaFuncAttributeMaxDynamicSharedMemorySize, SMEM_G1);
    cudaFuncSetAttribute(gemm2_mma, cudaFuncAttributeMaxDynamicSharedMemorySize, SMEM_G2);

    prep_kernel<<<Kc + PREP_XBLK, 256>>>(C, X);                       // fused C+X prep

    gemm1_mma<<<dim3(Kc / 128, Mc / 128), 256, SMEM_G1>>>();          // (4, 256)

    softmaxT_kernel<<<dim3(Mc / 128, Kc / 64), 256>>>();              // (256, 8)

    gemm2_mma<<<dim3(Dc / 128, Kc / 128, Bc), 256, SMEM_G2>>>(out);   // (6, 4, 32)
}